// round 14
// baseline (speedup 1.0000x reference)
#include <cuda_runtime.h>
#include <math.h>

#define H 1024
#define F 128
#define F4 32
#define MAXS 8192
#define NB 560           // kQ blocks
#define CBLK 128         // kC blocks

// Scratch (rewritten every call; flagC reset by k4h second half).
__device__ float g_partial[NB * H];
__device__ float g_qp[CBLK * F];
__device__ float g_w[2];
__device__ float g_v0[H];
__device__ float g_v1[H];
__device__ float g_r0[MAXS];
__device__ float g_r1[MAXS];
__device__ int   g_flagC;

// ---------------------------------------------------------------------------
__device__ __forceinline__ void compute_mem(float* mem,
                                            const float* ts, const float* dg,
                                            const float* Wt1, const float* bt1,
                                            const float* Wt2, const float* bt2,
                                            int t) {
    int k = t >> 7, h = t & 127;
    float tk = ts[k];
    float acc = bt2[h];
    #pragma unroll
    for (int j = 0; j < F4; ++j) {
        float a = fmaxf(fmaf(tk, Wt1[j], bt1[j]), 0.f);
        acc = fmaf(a, Wt2[j * F + h], acc);
    }
    mem[t] = dg[k * F + h] + acc;
}

// ---------------------------------------------------------------------------
// kA: 32 blocks -> v0/v1 (Wg^T mem_k + bg).
// ---------------------------------------------------------------------------
__global__ void kA(const float* __restrict__ ts,  const float* __restrict__ dg,
                   const float* __restrict__ Wt1, const float* __restrict__ bt1,
                   const float* __restrict__ Wt2, const float* __restrict__ bt2,
                   const float* __restrict__ Wg,  const float* __restrict__ bg) {
    __shared__ float mem[2 * F];
    __shared__ float s0[256];
    __shared__ float s1[256];
    int t = threadIdx.x, b = blockIdx.x;
    compute_mem(mem, ts, dg, Wt1, bt1, Wt2, bt2, t);
    __syncthreads();
    int hcol = b * 32 + (t & 31);
    int fg = t >> 5;
    float a0 = 0.f, a1 = 0.f;
    #pragma unroll
    for (int f = fg * 16; f < fg * 16 + 16; ++f) {
        float w = Wg[(size_t)f * H + hcol];
        a0 = fmaf(mem[f], w, a0);
        a1 = fmaf(mem[F + f], w, a1);
    }
    s0[t] = a0; s1[t] = a1;
    __syncthreads();
    if (t < 128) { s0[t] += s0[t + 128]; s1[t] += s1[t + 128]; }
    __syncthreads();
    if (t < 64)  { s0[t] += s0[t + 64];  s1[t] += s1[t + 64]; }
    __syncthreads();
    if (t < 32) {
        float bb = bg[hcol];
        g_v0[hcol] = s0[t] + s0[t + 32] + bb;
        g_v1[hcol] = s1[t] + s1[t + 32] + bb;
    }
}

// ---------------------------------------------------------------------------
// kE: dual key matvec for rows [r0, r0+cnt). Warp per row, static.
// ---------------------------------------------------------------------------
__global__ void kE(const float4* __restrict__ key4, int r0, int cnt) {
    int w = blockIdx.x * 8 + (threadIdx.x >> 5);
    int lane = threadIdx.x & 31;
    if (w >= cnt) return;
    int row = r0 + w;
    const float4* k4p = key4 + (size_t)row * (H / 4);
    const float4* v04 = (const float4*)g_v0;
    const float4* v14 = (const float4*)g_v1;
    float a0 = 0.f, a1 = 0.f;
    #pragma unroll
    for (int i = 0; i < (H / 4) / 32; ++i) {
        int idx = i * 32 + lane;
        float4 kv = __ldcs(k4p + idx);
        float4 x = __ldg(v04 + idx);
        float4 y = __ldg(v14 + idx);
        a0 = fmaf(kv.x, x.x, a0); a0 = fmaf(kv.y, x.y, a0);
        a0 = fmaf(kv.z, x.z, a0); a0 = fmaf(kv.w, x.w, a0);
        a1 = fmaf(kv.x, y.x, a1); a1 = fmaf(kv.y, y.y, a1);
        a1 = fmaf(kv.z, y.z, a1); a1 = fmaf(kv.w, y.w, a1);
    }
    #pragma unroll
    for (int off = 16; off; off >>= 1) {
        a0 += __shfl_xor_sync(0xFFFFFFFFu, a0, off);
        a1 += __shfl_xor_sync(0xFFFFFFFFu, a1, off);
    }
    if (lane == 0) { g_r0[row] = a0; g_r1[row] = a1; }
}

// ---------------------------------------------------------------------------
// kQ: query column partial sums over NB static slices.
// ---------------------------------------------------------------------------
__global__ void kQ(const float4* __restrict__ q4, int S) {
    int b = blockIdx.x, t = threadIdx.x;
    int rpb = (S + NB - 1) / NB;
    int r0 = b * rpb;
    int r1 = min(S, r0 + rpb);
    float4 acc = make_float4(0.f, 0.f, 0.f, 0.f);
    for (int r = r0; r < r1; ++r) {
        float4 v = __ldcs(q4 + (size_t)r * (H / 4) + t);
        acc.x += v.x; acc.y += v.y; acc.z += v.z; acc.w += v.w;
    }
    ((float4*)g_partial)[(size_t)b * (H / 4) + t] = acc;
}

// ---------------------------------------------------------------------------
// kC: 128 blocks; block cb reduces its 8-h qmean slice + qpart partial;
// last ticket block finishes scores -> g_w.
// ---------------------------------------------------------------------------
__global__ void kC(const float* __restrict__ ts,  const float* __restrict__ dg,
                   const float* __restrict__ Wt1, const float* __restrict__ bt1,
                   const float* __restrict__ Wt2, const float* __restrict__ bt2,
                   const float* __restrict__ Wa1, const float* __restrict__ ba1,
                   const float* __restrict__ Wa2, const float* __restrict__ ba2,
                   int S) {
    __shared__ float s0[256];
    __shared__ float mem[2 * F];
    __shared__ float qm[8];
    __shared__ float qpart[F];
    __shared__ int slast;
    int cb = blockIdx.x, t = threadIdx.x;
    int h0 = cb * 8;
    {
        int hl = t & 7, pl = t >> 3;
        float s = 0.f;
        for (int p = pl; p < NB; p += 32)
            s += g_partial[p * H + h0 + hl];
        s0[t] = s;
        __syncthreads();
        #pragma unroll
        for (int off = 128; off >= 8; off >>= 1) {
            if (t < off) s0[t] += s0[t + off];
            __syncthreads();
        }
        if (t < 8) qm[t] = s0[t] / (float)S;
        __syncthreads();
    }
    {
        int j = t & 127, half = t >> 7;
        float acc = 0.f;
        #pragma unroll
        for (int hl = half * 4; hl < half * 4 + 4; ++hl)
            acc = fmaf(qm[hl], Wa1[(size_t)(F + h0 + hl) * F + j], acc);
        s0[t] = acc;
        __syncthreads();
        if (t < 128) g_qp[cb * F + t] = s0[t] + s0[t + 128];
    }
    __threadfence();
    __syncthreads();
    if (t == 0) slast = (atomicAdd(&g_flagC, 1) == CBLK - 1);
    __syncthreads();
    if (!slast) return;

    __threadfence();
    {
        int j = t & 127, half = t >> 7;
        float s = 0.f;
        for (int bb = half * (CBLK / 2); bb < (half + 1) * (CBLK / 2); ++bb)
            s += __ldcg(&g_qp[bb * F + j]);
        s0[t] = s;
    }
    compute_mem(mem, ts, dg, Wt1, bt1, Wt2, bt2, t);
    __syncthreads();
    if (t < F) qpart[t] = s0[t] + s0[t + F];
    __syncthreads();
    {
        int k = t >> 7, j = t & 127;
        float acc = ba1[j] + qpart[j];
        #pragma unroll 8
        for (int f = 0; f < F; ++f)
            acc = fmaf(mem[k * F + f], Wa1[(size_t)f * F + j], acc);
        s0[t] = tanhf(acc) * Wa2[j];
    }
    __syncthreads();
    for (int off = 64; off; off >>= 1) {
        if ((t & 127) < off) s0[t] += s0[t + off];
        __syncthreads();
    }
    if ((t & 127) == 0)
        g_w[t >> 7] = 0.5f / (1.f + expf(-(s0[t] + ba2[0])));
}

// ---------------------------------------------------------------------------
// k4h: out[row][c0 .. c0+cols) = w0*r0[c] + w1*r1[c]. One block per row.
// reset != 0 -> also reset flagC (done by the last half).
// ---------------------------------------------------------------------------
__global__ void k4h(float* __restrict__ out, int S, int c0, int cols, int reset) {
    if (reset && blockIdx.x == 0 && threadIdx.x == 0) g_flagC = 0;
    __shared__ float wsh[2];
    if (threadIdx.x < 2) wsh[threadIdx.x] = g_w[threadIdx.x];
    __syncthreads();
    float w0 = wsh[0], w1 = wsh[1];
    int row = blockIdx.x;
    const float4* r04 = (const float4*)(g_r0 + c0);
    const float4* r14 = (const float4*)(g_r1 + c0);
    float4* o4 = (float4*)(out + (size_t)row * S + c0);
    int n4 = cols >> 2;
    for (int c = threadIdx.x; c < n4; c += blockDim.x) {
        float4 a = __ldg(r04 + c);
        float4 b = __ldg(r14 + c);
        float4 v;
        v.x = fmaf(w0, a.x, w1 * b.x);
        v.y = fmaf(w0, a.y, w1 * b.y);
        v.z = fmaf(w0, a.z, w1 * b.z);
        v.w = fmaf(w0, a.w, w1 * b.w);
        __stcs(o4 + c, v);
    }
}

// ---------------------------------------------------------------------------
extern "C" void kernel_launch(void* const* d_in, const int* in_sizes, int n_in,
                              void* d_out, int out_size) {
    const float* query = (const float*)d_in[0];
    const float* key   = (const float*)d_in[1];
    const float* dg    = (const float*)d_in[2];
    const float* ts    = (const float*)d_in[3];
    const float* Wt1   = (const float*)d_in[4];
    const float* bt1   = (const float*)d_in[5];
    const float* Wt2   = (const float*)d_in[6];
    const float* bt2   = (const float*)d_in[7];
    const float* Wa1   = (const float*)d_in[8];
    const float* ba1   = (const float*)d_in[9];
    const float* Wa2   = (const float*)d_in[10];
    const float* ba2   = (const float*)d_in[11];
    const float* Wg    = (const float*)d_in[12];
    const float* bg    = (const float*)d_in[13];

    int S = in_sizes[1] / H;
    int half = S / 2;

    static cudaStream_t sA = nullptr;
    static cudaEvent_t evFork = nullptr, evE0 = nullptr, evE1 = nullptr;
    if (!sA) {
        cudaStreamCreateWithFlags(&sA, cudaStreamNonBlocking);
        cudaEventCreateWithFlags(&evFork, cudaEventDisableTiming);
        cudaEventCreateWithFlags(&evE0, cudaEventDisableTiming);
        cudaEventCreateWithFlags(&evE1, cudaEventDisableTiming);
    }

    cudaEventRecord(evFork, 0);
    cudaStreamWaitEvent(sA, evFork, 0);

    // Side stream: v0/v1 then key matvec in two row-halves.
    kA<<<32, 256, 0, sA>>>(ts, dg, Wt1, bt1, Wt2, bt2, Wg, bg);
    kE<<<(half + 7) / 8, 256, 0, sA>>>((const float4*)key, 0, half);
    cudaEventRecord(evE0, sA);
    kE<<<(S - half + 7) / 8, 256, 0, sA>>>((const float4*)key, half, S - half);
    cudaEventRecord(evE1, sA);

    // Main stream: query-side weights, then the two column-half broadcasts.
    kQ<<<NB, 256>>>((const float4*)query, S);
    kC<<<CBLK, 256>>>(ts, dg, Wt1, bt1, Wt2, bt2, Wa1, ba1, Wa2, ba2, S);
    cudaStreamWaitEvent(0, evE0, 0);
    k4h<<<S, 256>>>((float*)d_out, S, 0, half, 0);
    cudaStreamWaitEvent(0, evE1, 0);
    k4h<<<S, 256>>>((float*)d_out, S, half, S - half, 1);
}

// round 16
// speedup vs baseline: 1.1903x; 1.1903x over previous
#include <cuda_runtime.h>
#include <math.h>

#define H 1024
#define F 128
#define F4 32
#define MAXS 8192
#define G 592            // 148 SMs x 4 blocks — all-resident by construction
#define ABLK 32          // blocks doing phase A
#define CBLK 128         // blocks doing the qpart stage
#define BCNT (G - ABLK)  // blocks doing query colsum
#define CH 8             // E rows per dynamic grab (one per warp)

// Scratch (rewritten every call; counters reset by k4 => deterministic).
__device__ float g_partial[G * H];
__device__ float g_qp[CBLK * F];
__device__ float g_w[2];
__device__ float g_v0[H];
__device__ float g_v1[H];
__device__ float g_r0[MAXS];
__device__ float g_r1[MAXS];
__device__ int   g_flagA;
__device__ int   g_flagB;
__device__ int   g_flagC;
__device__ int   g_rowctr;

// ---------------------------------------------------------------------------
__device__ __forceinline__ void compute_mem(float* mem,
                                            const float* ts, const float* dg,
                                            const float* Wt1, const float* bt1,
                                            const float* Wt2, const float* bt2,
                                            int t) {
    int k = t >> 7, h = t & 127;
    float tk = ts[k];
    float acc = bt2[h];
    #pragma unroll
    for (int j = 0; j < F4; ++j) {
        float a = fmaxf(fmaf(tk, Wt1[j], bt1[j]), 0.f);
        acc = fmaf(a, Wt2[j * F + h], acc);
    }
    mem[t] = dg[k * F + h] + acc;
}

// ---------------------------------------------------------------------------
// C-stage: block b (<CBLK) reduces its 8-h qmean slice and qpart partial;
// last ticket block finishes scores -> g_w.
// ---------------------------------------------------------------------------
__device__ void do_stage_C(int b, int t, float* s0, float* mem, float* qm,
                           float* qpart, int* slast,
                           const float* ts,  const float* dg,
                           const float* Wt1, const float* bt1,
                           const float* Wt2, const float* bt2,
                           const float* Wa1, const float* ba1,
                           const float* Wa2, const float* ba2, int S) {
    __threadfence();
    int h0 = b * 8;
    {
        int hl = t & 7, pl = t >> 3;
        float s = 0.f;
        for (int p = ABLK + pl; p < G; p += 32)   // only blocks >=ABLK wrote partials
            s += g_partial[p * H + h0 + hl];
        s0[t] = s;
        __syncthreads();
        #pragma unroll
        for (int off = 128; off >= 8; off >>= 1) {
            if (t < off) s0[t] += s0[t + off];
            __syncthreads();
        }
        if (t < 8) qm[t] = s0[t] / (float)S;
        __syncthreads();
    }
    {
        int j = t & 127, half = t >> 7;
        float acc = 0.f;
        #pragma unroll
        for (int hl = half * 4; hl < half * 4 + 4; ++hl)
            acc = fmaf(qm[hl], Wa1[(size_t)(F + h0 + hl) * F + j], acc);
        s0[t] = acc;
        __syncthreads();
        if (t < 128) g_qp[b * F + t] = s0[t] + s0[t + 128];
    }
    __threadfence();
    __syncthreads();
    if (t == 0) *slast = (atomicAdd(&g_flagC, 1) == CBLK - 1);
    __syncthreads();
    if (!*slast) return;

    __threadfence();
    {
        int j = t & 127, half = t >> 7;
        float s = 0.f;
        for (int bb = half * (CBLK / 2); bb < (half + 1) * (CBLK / 2); ++bb)
            s += __ldcg(&g_qp[bb * F + j]);
        s0[t] = s;
    }
    compute_mem(mem, ts, dg, Wt1, bt1, Wt2, bt2, t);
    __syncthreads();
    if (t < F) qpart[t] = s0[t] + s0[t + F];
    __syncthreads();
    {
        int k = t >> 7, j = t & 127;
        float acc = ba1[j] + qpart[j];
        #pragma unroll 8
        for (int f = 0; f < F; ++f)
            acc = fmaf(mem[k * F + f], Wa1[(size_t)f * F + j], acc);
        s0[t] = tanhf(acc) * Wa2[j];
    }
    __syncthreads();
    for (int off = 64; off; off >>= 1) {
        if ((t & 127) < off) s0[t] += s0[t + off];
        __syncthreads();
    }
    if ((t & 127) == 0)
        g_w[t >> 7] = 0.5f / (1.f + expf(-(s0[t] + ba2[0])));
}

// ---------------------------------------------------------------------------
__global__ void __launch_bounds__(256, 4)
kPre(const float4* __restrict__ q4, const float4* __restrict__ key4,
     const float* __restrict__ ts,  const float* __restrict__ dg,
     const float* __restrict__ Wt1, const float* __restrict__ bt1,
     const float* __restrict__ Wt2, const float* __restrict__ bt2,
     const float* __restrict__ Wa1, const float* __restrict__ ba1,
     const float* __restrict__ Wa2, const float* __restrict__ ba2,
     const float* __restrict__ Wg,  const float* __restrict__ bg,
     int S) {
    __shared__ float s0[256];
    __shared__ float s1[256];
    __shared__ float mem[2 * F];
    __shared__ float qm[8];
    __shared__ float qpart[F];
    __shared__ int slast;
    __shared__ int sh_row;
    __shared__ int sh_ready;

    int t = threadIdx.x, b = blockIdx.x;

    if (b < ABLK) {
        // ---- A: v0/v1 h-slices (Wg^T mem + bg); skip B ----
        compute_mem(mem, ts, dg, Wt1, bt1, Wt2, bt2, t);
        __syncthreads();
        int hcol = b * 32 + (t & 31);
        int fg = t >> 5;
        float a0 = 0.f, a1 = 0.f;
        #pragma unroll
        for (int f = fg * 16; f < fg * 16 + 16; ++f) {
            float w = Wg[(size_t)f * H + hcol];
            a0 = fmaf(mem[f], w, a0);
            a1 = fmaf(mem[F + f], w, a1);
        }
        s0[t] = a0; s1[t] = a1;
        __syncthreads();
        if (t < 128) { s0[t] += s0[t + 128]; s1[t] += s1[t + 128]; }
        __syncthreads();
        if (t < 64)  { s0[t] += s0[t + 64];  s1[t] += s1[t + 64]; }
        __syncthreads();
        if (t < 32) {
            float bb = bg[hcol];
            g_v0[hcol] = s0[t] + s0[t + 32] + bb;
            g_v1[hcol] = s1[t] + s1[t + 32] + bb;
        }
        __threadfence();
        __syncthreads();
        if (t == 0) atomicAdd(&g_flagA, 1);
        __syncthreads();
    } else {
        // ---- B: query column partial sums, 4-way unrolled (MLP >= 4) ----
        int bb = b - ABLK;
        int rpb = (S + BCNT - 1) / BCNT;
        int r0 = bb * rpb;
        int r1 = min(S, r0 + rpb);
        const float4* qp = q4 + (size_t)r0 * (H / 4) + t;
        float4 a0 = make_float4(0.f, 0.f, 0.f, 0.f);
        float4 a1 = make_float4(0.f, 0.f, 0.f, 0.f);
        float4 a2 = make_float4(0.f, 0.f, 0.f, 0.f);
        float4 a3 = make_float4(0.f, 0.f, 0.f, 0.f);
        int r = r0;
        for (; r + 4 <= r1; r += 4) {
            float4 v0 = __ldcs(qp);
            float4 v1 = __ldcs(qp + (H / 4));
            float4 v2 = __ldcs(qp + 2 * (H / 4));
            float4 v3 = __ldcs(qp + 3 * (H / 4));
            a0.x += v0.x; a0.y += v0.y; a0.z += v0.z; a0.w += v0.w;
            a1.x += v1.x; a1.y += v1.y; a1.z += v1.z; a1.w += v1.w;
            a2.x += v2.x; a2.y += v2.y; a2.z += v2.z; a2.w += v2.w;
            a3.x += v3.x; a3.y += v3.y; a3.z += v3.z; a3.w += v3.w;
            qp += 4 * (H / 4);
        }
        for (; r < r1; ++r) {
            float4 v0 = __ldcs(qp);
            a0.x += v0.x; a0.y += v0.y; a0.z += v0.z; a0.w += v0.w;
            qp += (H / 4);
        }
        float4 acc;
        acc.x = (a0.x + a1.x) + (a2.x + a3.x);
        acc.y = (a0.y + a1.y) + (a2.y + a3.y);
        acc.z = (a0.z + a1.z) + (a2.z + a3.z);
        acc.w = (a0.w + a1.w) + (a2.w + a3.w);
        ((float4*)g_partial)[b * (H / 4) + t] = acc;
        __threadfence();
        __syncthreads();
        if (t == 0) atomicAdd(&g_flagB, 1);
        __syncthreads();
    }

    // ---- wait for v0/v1 (producers finish early) ----
    if (t == 0) {
        while (*(volatile int*)&g_flagA < ABLK) __nanosleep(64);
    }
    __syncthreads();
    __threadfence();

    // ---- E: dynamic dual key matvec, with C-stage poll-interleave ----
    bool needC = (b < CBLK);
    int lane = t & 31, wid = t >> 5;
    const float4* v04 = (const float4*)g_v0;
    const float4* v14 = (const float4*)g_v1;

    for (;;) {
        if (needC) {
            if (t == 0) sh_ready = (*(volatile int*)&g_flagB >= BCNT);
            __syncthreads();
            if (sh_ready) {
                do_stage_C(b, t, s0, mem, qm, qpart, &slast,
                           ts, dg, Wt1, bt1, Wt2, bt2, Wa1, ba1, Wa2, ba2, S);
                needC = false;
                __syncthreads();
            }
        }
        if (t == 0) sh_row = atomicAdd(&g_rowctr, CH);
        __syncthreads();
        int row0 = sh_row;
        if (row0 >= S) break;
        int row = row0 + wid;
        if (row < S) {
            const float4* k4p = key4 + (size_t)row * (H / 4);
            float a0 = 0.f, a1 = 0.f;
            #pragma unroll
            for (int i = 0; i < (H / 4) / 32; ++i) {
                int idx = i * 32 + lane;
                float4 kv = __ldcs(k4p + idx);
                float4 x = __ldg(v04 + idx);
                float4 y = __ldg(v14 + idx);
                a0 = fmaf(kv.x, x.x, a0); a0 = fmaf(kv.y, x.y, a0);
                a0 = fmaf(kv.z, x.z, a0); a0 = fmaf(kv.w, x.w, a0);
                a1 = fmaf(kv.x, y.x, a1); a1 = fmaf(kv.y, y.y, a1);
                a1 = fmaf(kv.z, y.z, a1); a1 = fmaf(kv.w, y.w, a1);
            }
            #pragma unroll
            for (int off = 16; off; off >>= 1) {
                a0 += __shfl_xor_sync(0xFFFFFFFFu, a0, off);
                a1 += __shfl_xor_sync(0xFFFFFFFFu, a1, off);
            }
            if (lane == 0) { g_r0[row] = a0; g_r1[row] = a1; }
        }
        __syncthreads();
    }

    // If C never became ready during the row loop, finish it now.
    if (needC) {
        if (t == 0) {
            while (*(volatile int*)&g_flagB < BCNT) __nanosleep(64);
        }
        __syncthreads();
        do_stage_C(b, t, s0, mem, qm, qpart, &slast,
                   ts, dg, Wt1, bt1, Wt2, bt2, Wa1, ba1, Wa2, ba2, S);
    }
}

// ---------------------------------------------------------------------------
// K4: out[row][s] = w0*r0[s] + w1*r1[s]; resets counters for graph replay.
// ---------------------------------------------------------------------------
__global__ void k4_bcast(float* __restrict__ out, int S) {
    if (blockIdx.x == 0 && threadIdx.x == 0) {
        g_flagA = 0; g_flagB = 0; g_flagC = 0; g_rowctr = 0;
    }
    __shared__ float wsh[2];
    if (threadIdx.x < 2) wsh[threadIdx.x] = g_w[threadIdx.x];
    __syncthreads();
    float w0 = wsh[0], w1 = wsh[1];
    int row = blockIdx.x;
    const float4* r04 = (const float4*)g_r0;
    const float4* r14 = (const float4*)g_r1;
    float4* o4 = (float4*)(out + (size_t)row * S);
    int n4 = S >> 2;
    for (int c = threadIdx.x; c < n4; c += blockDim.x) {
        float4 a = __ldg(r04 + c);
        float4 b = __ldg(r14 + c);
        float4 v;
        v.x = fmaf(w0, a.x, w1 * b.x);
        v.y = fmaf(w0, a.y, w1 * b.y);
        v.z = fmaf(w0, a.z, w1 * b.z);
        v.w = fmaf(w0, a.w, w1 * b.w);
        __stcs(o4 + c, v);
    }
}

// ---------------------------------------------------------------------------
extern "C" void kernel_launch(void* const* d_in, const int* in_sizes, int n_in,
                              void* d_out, int out_size) {
    const float* query = (const float*)d_in[0];
    const float* key   = (const float*)d_in[1];
    const float* dg    = (const float*)d_in[2];
    const float* ts    = (const float*)d_in[3];
    const float* Wt1   = (const float*)d_in[4];
    const float* bt1   = (const float*)d_in[5];
    const float* Wt2   = (const float*)d_in[6];
    const float* bt2   = (const float*)d_in[7];
    const float* Wa1   = (const float*)d_in[8];
    const float* ba1   = (const float*)d_in[9];
    const float* Wa2   = (const float*)d_in[10];
    const float* ba2   = (const float*)d_in[11];
    const float* Wg    = (const float*)d_in[12];
    const float* bg    = (const float*)d_in[13];

    int S = in_sizes[1] / H;

    kPre<<<G, 256>>>((const float4*)query, (const float4*)key,
                     ts, dg, Wt1, bt1, Wt2, bt2,
                     Wa1, ba1, Wa2, ba2, Wg, bg, S);
    k4_bcast<<<S, 256>>>((float*)d_out, S);
}